// round 2
// baseline (speedup 1.0000x reference)
#include <cuda_runtime.h>
#include <cuda_bf16.h>

#define BB 256
#define TT 512
#define DD 64
#define HH 128

// ---------------- device scratch (static, no allocation) ----------------
__device__ __nv_bfloat16 g_s2[(size_t)BB * DD * TT];   // 16.8 MB, [b][d][s]
__device__ __nv_bfloat16 g_w1p[32 * 512 * 8];          // [kk][s][u], k = kk*8+u in [0,256)
__device__ __nv_bfloat16 g_wzp[24 * 512 * 8];          // [kk][j][u], k' in [0,192): 0..63 Wih, 64..191 Whh

// ---------------- helpers ----------------
__device__ __forceinline__ float tanh_fast(float x) {
    float y;
    asm("tanh.approx.f32 %0, %1;" : "=f"(y) : "f"(x));
    return y;
}
__device__ __forceinline__ float bl(unsigned u) { return __uint_as_float(u << 16); }
__device__ __forceinline__ float bh(unsigned u) { return __uint_as_float(u & 0xffff0000u); }
__device__ __forceinline__ float sigf(float x) { return 1.f / (1.f + __expf(-x)); }
__device__ __forceinline__ float tanh_ex(float x) {
    x = fminf(fmaxf(x, -15.f), 15.f);
    float e = __expf(2.f * x);
    return (e - 1.f) / (e + 1.f);
}
__device__ __forceinline__ unsigned pack_bf2(float a, float b) {
    __nv_bfloat162 t = __floats2bfloat162_rn(a, b);
    return *(unsigned*)&t;
}

// ---------------- kernel 1: pack weights to bf16, coalesced layout ----------------
__global__ void pack_weights(const float* __restrict__ W1, const float* __restrict__ Wih,
                             const float* __restrict__ Whh) {
    int idx = blockIdx.x * blockDim.x + threadIdx.x;
    int stride = gridDim.x * blockDim.x;
    for (int i = idx; i < 32 * 512 * 8; i += stride) {
        int u = i & 7, s = (i >> 3) & 511, kk = i >> 12;
        g_w1p[i] = __float2bfloat16(W1[s * 256 + kk * 8 + u]);
    }
    for (int i = idx; i < 24 * 512 * 8; i += stride) {
        int u = i & 7, j = (i >> 3) & 511, kk = i >> 12;
        int k = kk * 8 + u;
        float v = (k < 64) ? Wih[j * 64 + k] : Whh[j * 128 + (k - 64)];
        g_wzp[i] = __float2bfloat16(v);
    }
}

// ---------------- kernel 2: s2[b,d,s] = sum_t din[b,t,d]*W2[s,t] + b2[s] ----------------
__global__ void __launch_bounds__(256) s2_gemm(const float* __restrict__ din,
                                               const float* __restrict__ W2,
                                               const float* __restrict__ b2) {
    __shared__ float dint[64 * 64];    // [tt][d]
    __shared__ float w2t[64 * 144];    // [tt][sl], pad 144 (16B aligned, 2-way store conflict only)
    int bx = blockIdx.x;
    int b = bx >> 2;
    int s0 = (bx & 3) << 7;            // 128 s per block
    int tid = threadIdx.x;
    int d = tid & 63, ssub = tid >> 6; // ssub in 0..3, 32 s each

    float acc[32];
#pragma unroll
    for (int q = 0; q < 32; q++) acc[q] = b2[s0 + ssub * 32 + q];

    for (int tc = 0; tc < 8; tc++) {
        int t0 = tc * 64;
        __syncthreads();
        for (int i = tid; i < 64 * 64; i += 256) {
            int tt = i >> 6, dd = i & 63;
            dint[i] = din[((size_t)b * TT + t0 + tt) * DD + dd];
        }
        for (int i = tid; i < 128 * 64; i += 256) {
            int sl = i >> 6, tt = i & 63;
            w2t[tt * 144 + sl] = W2[(size_t)(s0 + sl) * TT + t0 + tt];
        }
        __syncthreads();
        for (int tt = 0; tt < 64; tt++) {
            float av = dint[tt * 64 + d];
            const float4* wp = (const float4*)&w2t[tt * 144 + ssub * 32];
#pragma unroll
            for (int q = 0; q < 8; q++) {
                float4 w = wp[q];
                acc[q * 4 + 0] = fmaf(av, w.x, acc[q * 4 + 0]);
                acc[q * 4 + 1] = fmaf(av, w.y, acc[q * 4 + 1]);
                acc[q * 4 + 2] = fmaf(av, w.z, acc[q * 4 + 2]);
                acc[q * 4 + 3] = fmaf(av, w.w, acc[q * 4 + 3]);
            }
        }
    }
    uint4 o[4];
    unsigned* ow = (unsigned*)o;
#pragma unroll
    for (int q = 0; q < 16; q++) ow[q] = pack_bf2(acc[2 * q], acc[2 * q + 1]);
    uint4* dst = (uint4*)(g_s2 + ((size_t)(b * 64 + d)) * TT + s0 + ssub * 32);
    dst[0] = o[0]; dst[1] = o[1]; dst[2] = o[2]; dst[3] = o[3];
}

// ---------------- kernel 3: the scan ----------------
#define S2STRIDE 544   // bf16 elems per (b,d) row in SMEM; 1088B -> +16 bank shift per row

// SMEM layout (floats after the bf16 s2 slice)
#define SM_S2_BYTES (2 * 64 * S2STRIDE * 2)

__global__ void __launch_bounds__(512, 1) scan_kernel(
    const float* __restrict__ din, const float* __restrict__ b1,
    const float* __restrict__ bih, const float* __restrict__ bhh,
    const float* __restrict__ W3, const float* __restrict__ b3,
    float* __restrict__ out) {
    extern __shared__ char smraw[];
    __nv_bfloat16* s2s = (__nv_bfloat16*)smraw;          // [2*64][544]
    float* hc  = (float*)(smraw + SM_S2_BYTES);           // [2][256] : h then c
    float* s1s = hc + 2 * 256;                            // [2][512]
    float* zs  = s1s + 2 * 512;                           // [2][512]
    float* xs  = zs + 2 * 512;                            // [2][64]
    float* es  = xs + 2 * 64;                             // [2][64]
    float* w3s = es + 2 * 64;                             // [512]
    float* b1s = w3s + 512;                               // [512]
    float* bzs = b1s + 512;                               // [512]

    const int tid = threadIdx.x;
    const int b0 = blockIdx.x * 2;

    // init constants
    w3s[tid] = W3[tid];
    b1s[tid] = b1[tid];
    bzs[tid] = bih[tid] + bhh[tid];
    hc[tid] = 0.f;   // 512 floats = [2][256]

    // load s2 slice into SMEM (padded rows)
    for (int bb = 0; bb < 2; bb++) {
        const uint4* src = (const uint4*)(g_s2 + (size_t)(b0 + bb) * DD * TT);
        for (int i = tid; i < 64 * 64; i += 512) {
            int r = i >> 6, cc = i & 63;
            *((uint4*)(s2s + (size_t)(bb * 64 + r) * S2STRIDE + cc * 8)) = src[i];
        }
    }
    __syncthreads();
    const float b3v = b3[0];

    for (int t = 0; t < TT; t++) {
        // ---- Phase A: s1[b][s] = hc[b] . W1row[s] + b1[s] ----
        {
            const int s = tid;
            const uint4* wp = (const uint4*)g_w1p;
            const float4* h0 = (const float4*)hc;
            const float4* h1 = (const float4*)(hc + 256);
            float a0 = 0.f, a1 = 0.f;
#pragma unroll 8
            for (int kk = 0; kk < 32; kk++) {
                uint4 w = wp[kk * 512 + s];
                float4 pa = h0[kk * 2], pb = h0[kk * 2 + 1];
                float4 qa = h1[kk * 2], qb = h1[kk * 2 + 1];
                float w0 = bl(w.x), w1 = bh(w.x), w2 = bl(w.y), w3v_ = bh(w.y);
                float w4 = bl(w.z), w5 = bh(w.z), w6 = bl(w.w), w7 = bh(w.w);
                a0 = fmaf(w0, pa.x, a0); a0 = fmaf(w1, pa.y, a0);
                a0 = fmaf(w2, pa.z, a0); a0 = fmaf(w3v_, pa.w, a0);
                a0 = fmaf(w4, pb.x, a0); a0 = fmaf(w5, pb.y, a0);
                a0 = fmaf(w6, pb.z, a0); a0 = fmaf(w7, pb.w, a0);
                a1 = fmaf(w0, qa.x, a1); a1 = fmaf(w1, qa.y, a1);
                a1 = fmaf(w2, qa.z, a1); a1 = fmaf(w3v_, qa.w, a1);
                a1 = fmaf(w4, qb.x, a1); a1 = fmaf(w5, qb.y, a1);
                a1 = fmaf(w6, qb.z, a1); a1 = fmaf(w7, qb.w, a1);
            }
            s1s[s] = a0 + b1s[s];
            s1s[512 + s] = a1 + b1s[s];
        }
        __syncthreads();

        // ---- Phase B: e[b][d] = sum_s tanh(s1+s2)*w3 + b3 ----
        {
            const int p = tid >> 2, sub = tid & 3;
            const int bb = p >> 6, d = p & 63;
            const uint4* row = (const uint4*)(s2s + (size_t)(bb * 64 + d) * S2STRIDE);
            const float4* s1f = (const float4*)(s1s + bb * 512);
            const float4* w3f = (const float4*)w3s;
            float acc = 0.f;
#pragma unroll
            for (int it = 0; it < 16; it++) {
                uint4 v = row[it * 4 + sub];
                int f4 = it * 8 + sub * 2;
                float4 sa = s1f[f4], sb = s1f[f4 + 1];
                float4 wa = w3f[f4], wb = w3f[f4 + 1];
                acc = fmaf(tanh_fast(sa.x + bl(v.x)), wa.x, acc);
                acc = fmaf(tanh_fast(sa.y + bh(v.x)), wa.y, acc);
                acc = fmaf(tanh_fast(sa.z + bl(v.y)), wa.z, acc);
                acc = fmaf(tanh_fast(sa.w + bh(v.y)), wa.w, acc);
                acc = fmaf(tanh_fast(sb.x + bl(v.z)), wb.x, acc);
                acc = fmaf(tanh_fast(sb.y + bh(v.z)), wb.y, acc);
                acc = fmaf(tanh_fast(sb.z + bl(v.w)), wb.z, acc);
                acc = fmaf(tanh_fast(sb.w + bh(v.w)), wb.w, acc);
            }
            acc += __shfl_xor_sync(0xffffffffu, acc, 1);
            acc += __shfl_xor_sync(0xffffffffu, acc, 2);
            if (sub == 0) es[bb * 64 + d] = acc + b3v;
        }
        __syncthreads();

        // ---- Phase C: softmax over d, x = a * x_t ----
        if (tid < 64) {
            const int bb = tid >> 5, lane = tid & 31;
            float e0 = es[bb * 64 + lane], e1 = es[bb * 64 + lane + 32];
            float m = fmaxf(e0, e1);
#pragma unroll
            for (int o = 16; o; o >>= 1) m = fmaxf(m, __shfl_xor_sync(0xffffffffu, m, o));
            float p0 = __expf(e0 - m), p1 = __expf(e1 - m);
            float sm = p0 + p1;
#pragma unroll
            for (int o = 16; o; o >>= 1) sm += __shfl_xor_sync(0xffffffffu, sm, o);
            float inv = 1.f / sm;
            const float* dp = din + ((size_t)(b0 + bb) * TT + t) * DD;
            xs[bb * 64 + lane]      = p0 * inv * dp[lane];
            xs[bb * 64 + lane + 32] = p1 * inv * dp[lane + 32];
        }
        __syncthreads();

        // ---- Phase D: z[b][j] = x.Wih_row + h.Whh_row + bz ----
        {
            const int j = tid;
            const uint4* wp = (const uint4*)g_wzp;
            float a0 = 0.f, a1 = 0.f;
#pragma unroll
            for (int kk = 0; kk < 24; kk++) {
                uint4 w = wp[kk * 512 + j];
                float4 pa, pb, qa, qb;
                if (kk < 8) {
                    pa = ((const float4*)xs)[kk * 2];        pb = ((const float4*)xs)[kk * 2 + 1];
                    qa = ((const float4*)(xs + 64))[kk * 2]; qb = ((const float4*)(xs + 64))[kk * 2 + 1];
                } else {
                    pa = ((const float4*)hc)[(kk - 8) * 2];          pb = ((const float4*)hc)[(kk - 8) * 2 + 1];
                    qa = ((const float4*)(hc + 256))[(kk - 8) * 2];  qb = ((const float4*)(hc + 256))[(kk - 8) * 2 + 1];
                }
                float w0 = bl(w.x), w1 = bh(w.x), w2 = bl(w.y), w3v_ = bh(w.y);
                float w4 = bl(w.z), w5 = bh(w.z), w6 = bl(w.w), w7 = bh(w.w);
                a0 = fmaf(w0, pa.x, a0); a0 = fmaf(w1, pa.y, a0);
                a0 = fmaf(w2, pa.z, a0); a0 = fmaf(w3v_, pa.w, a0);
                a0 = fmaf(w4, pb.x, a0); a0 = fmaf(w5, pb.y, a0);
                a0 = fmaf(w6, pb.z, a0); a0 = fmaf(w7, pb.w, a0);
                a1 = fmaf(w0, qa.x, a1); a1 = fmaf(w1, qa.y, a1);
                a1 = fmaf(w2, qa.z, a1); a1 = fmaf(w3v_, qa.w, a1);
                a1 = fmaf(w4, qb.x, a1); a1 = fmaf(w5, qb.y, a1);
                a1 = fmaf(w6, qb.z, a1); a1 = fmaf(w7, qb.w, a1);
            }
            zs[j] = a0 + bzs[j];
            zs[512 + j] = a1 + bzs[j];
        }
        __syncthreads();

        // ---- Phase E: gates, state update, output ----
        if (tid < 256) {
            const int bb = tid >> 7, m = tid & 127;
            float iv = zs[bb * 512 + m];
            float fv = zs[bb * 512 + 128 + m];
            float gv = zs[bb * 512 + 256 + m];
            float ov = zs[bb * 512 + 384 + m];
            float c = hc[bb * 256 + 128 + m];
            float cn = sigf(fv) * c + sigf(iv) * tanh_ex(gv);
            float hn = sigf(ov) * tanh_ex(cn);
            hc[bb * 256 + 128 + m] = cn;
            hc[bb * 256 + m] = hn;
            out[(((size_t)(b0 + bb)) * TT + t) * HH + m] = hn;
        }
        __syncthreads();
    }
}

// ---------------- launch ----------------
extern "C" void kernel_launch(void* const* d_in, const int* in_sizes, int n_in,
                              void* d_out, int out_size) {
    const float* din = (const float*)d_in[0];
    const float* Wih = (const float*)d_in[1];
    const float* Whh = (const float*)d_in[2];
    const float* bih = (const float*)d_in[3];
    const float* bhh = (const float*)d_in[4];
    const float* W1  = (const float*)d_in[5];
    const float* b1  = (const float*)d_in[6];
    const float* W2  = (const float*)d_in[7];
    const float* b2  = (const float*)d_in[8];
    const float* W3  = (const float*)d_in[9];
    const float* b3  = (const float*)d_in[10];
    float* out = (float*)d_out;

    const int smem_bytes = SM_S2_BYTES + (2 * 256 + 2 * 512 + 2 * 512 + 2 * 64 + 2 * 64 + 3 * 512) * 4;
    cudaFuncSetAttribute(scan_kernel, cudaFuncAttributeMaxDynamicSharedMemorySize, smem_bytes);

    pack_weights<<<128, 256>>>(W1, Wih, Whh);
    s2_gemm<<<BB * 4, 256>>>(din, W2, b2);
    scan_kernel<<<BB / 2, 512, smem_bytes>>>(din, b1, bih, bhh, W3, b3, out);
}

// round 3
// speedup vs baseline: 1.0442x; 1.0442x over previous
#include <cuda_runtime.h>
#include <cuda_bf16.h>

#define BB 256
#define TT 512
#define DD 64
#define HH 128

// ---------------- device scratch (static, no allocation) ----------------
__device__ __nv_bfloat16 g_s2[(size_t)BB * DD * TT];   // 16.8 MB, [b][d][s]
__device__ __nv_bfloat16 g_w1p[32 * 512 * 8];          // [kk][s][u], k = kk*8+u in [0,256)
__device__ __nv_bfloat16 g_wzp[24 * 512 * 8];          // [kk][j][u], k' in [0,192): 0..63 Wih, 64..191 Whh

// ---------------- helpers ----------------
__device__ __forceinline__ float tanh_fast(float x) {
    float y;
    asm("tanh.approx.f32 %0, %1;" : "=f"(y) : "f"(x));
    return y;
}
__device__ __forceinline__ float bl(unsigned u) { return __uint_as_float(u << 16); }
__device__ __forceinline__ float bh(unsigned u) { return __uint_as_float(u & 0xffff0000u); }
__device__ __forceinline__ float sigf(float x) { return 1.f / (1.f + __expf(-x)); }
__device__ __forceinline__ float tanh_ex(float x) {
    x = fminf(fmaxf(x, -15.f), 15.f);
    float e = __expf(2.f * x);
    return (e - 1.f) / (e + 1.f);
}
__device__ __forceinline__ unsigned pack_bf2(float a, float b) {
    __nv_bfloat162 t = __floats2bfloat162_rn(a, b);
    return *(unsigned*)&t;
}

// f32x2 packed FMA: acc(pair) += ab(pair) * cd(pair)
__device__ __forceinline__ void ffma2(unsigned long long& acc, unsigned long long ab,
                                      unsigned long long cd) {
    asm("fma.rn.f32x2 %0, %1, %2, %0;" : "+l"(acc) : "l"(ab), "l"(cd));
}
// two bf16 (packed in u32) -> f32x2 pair {lo<<16, hi&mask}
__device__ __forceinline__ unsigned long long bfpair(unsigned u) {
    unsigned long long p;
    asm("{\n\t.reg .b32 lo, hi;\n\t"
        "shl.b32 lo, %1, 16;\n\t"
        "and.b32 hi, %1, 0xff" "ff0000;\n\t"
        "mov.b64 %0, {lo, hi};\n\t}" : "=l"(p) : "r"(u));
    return p;
}
__device__ __forceinline__ float pair_sum(unsigned long long p) {
    return __uint_as_float((unsigned)p) + __uint_as_float((unsigned)(p >> 32));
}

// ---------------- kernel 1: pack weights to bf16, coalesced layout ----------------
__global__ void pack_weights(const float* __restrict__ W1, const float* __restrict__ Wih,
                             const float* __restrict__ Whh) {
    int idx = blockIdx.x * blockDim.x + threadIdx.x;
    int stride = gridDim.x * blockDim.x;
    for (int i = idx; i < 32 * 512 * 8; i += stride) {
        int u = i & 7, s = (i >> 3) & 511, kk = i >> 12;
        g_w1p[i] = __float2bfloat16(W1[s * 256 + kk * 8 + u]);
    }
    for (int i = idx; i < 24 * 512 * 8; i += stride) {
        int u = i & 7, j = (i >> 3) & 511, kk = i >> 12;
        int k = kk * 8 + u;
        float v = (k < 64) ? Wih[j * 64 + k] : Whh[j * 128 + (k - 64)];
        g_wzp[i] = __float2bfloat16(v);
    }
}

// ---------------- kernel 2: s2[b,d,s] = sum_t din[b,t,d]*W2[s,t] + b2[s] ----------------
__global__ void __launch_bounds__(256) s2_gemm(const float* __restrict__ din,
                                               const float* __restrict__ W2,
                                               const float* __restrict__ b2) {
    __shared__ float dint[64 * 64];
    __shared__ float w2t[64 * 144];
    int bx = blockIdx.x;
    int b = bx >> 2;
    int s0 = (bx & 3) << 7;
    int tid = threadIdx.x;
    int d = tid & 63, ssub = tid >> 6;

    float acc[32];
#pragma unroll
    for (int q = 0; q < 32; q++) acc[q] = b2[s0 + ssub * 32 + q];

    for (int tc = 0; tc < 8; tc++) {
        int t0 = tc * 64;
        __syncthreads();
        for (int i = tid; i < 64 * 64; i += 256) {
            int tt = i >> 6, dd = i & 63;
            dint[i] = din[((size_t)b * TT + t0 + tt) * DD + dd];
        }
        for (int i = tid; i < 128 * 64; i += 256) {
            int sl = i >> 6, tt = i & 63;
            w2t[tt * 144 + sl] = W2[(size_t)(s0 + sl) * TT + t0 + tt];
        }
        __syncthreads();
        for (int tt = 0; tt < 64; tt++) {
            float av = dint[tt * 64 + d];
            const float4* wp = (const float4*)&w2t[tt * 144 + ssub * 32];
#pragma unroll
            for (int q = 0; q < 8; q++) {
                float4 w = wp[q];
                acc[q * 4 + 0] = fmaf(av, w.x, acc[q * 4 + 0]);
                acc[q * 4 + 1] = fmaf(av, w.y, acc[q * 4 + 1]);
                acc[q * 4 + 2] = fmaf(av, w.z, acc[q * 4 + 2]);
                acc[q * 4 + 3] = fmaf(av, w.w, acc[q * 4 + 3]);
            }
        }
    }
    uint4 o[4];
    unsigned* ow = (unsigned*)o;
#pragma unroll
    for (int q = 0; q < 16; q++) ow[q] = pack_bf2(acc[2 * q], acc[2 * q + 1]);
    uint4* dst = (uint4*)(g_s2 + ((size_t)(b * 64 + d)) * TT + s0 + ssub * 32);
    dst[0] = o[0]; dst[1] = o[1]; dst[2] = o[2]; dst[3] = o[3];
}

// ---------------- kernel 3: the scan ----------------
#define S2STRIDE 544
#define SM_S2_BYTES (2 * 64 * S2STRIDE * 2)   // 139264
#define SM_WIH_BYTES (8 * 512 * 8 * 2)         // 65536 (Wih cached in SMEM)

__global__ void __launch_bounds__(512, 1) scan_kernel(
    const float* __restrict__ din, const float* __restrict__ b1,
    const float* __restrict__ bih, const float* __restrict__ bhh,
    const float* __restrict__ W3, const float* __restrict__ b3,
    float* __restrict__ out) {
    extern __shared__ char smraw[];
    __nv_bfloat16* s2s = (__nv_bfloat16*)smraw;                 // [2*64][544]
    uint4* wihs = (uint4*)(smraw + SM_S2_BYTES);                // [8*512] uint4
    float* hc  = (float*)(smraw + SM_S2_BYTES + SM_WIH_BYTES);  // [2][256] : h then c
    float* s1s = hc + 2 * 256;                                   // [2][512]
    float* zhs = s1s + 2 * 512;                                  // [2][512]
    float* xs  = zhs + 2 * 512;                                  // [2][64]
    float* es  = xs + 2 * 64;                                    // [2][64]
    float* w3s = es + 2 * 64;                                    // [512]
    float* b1s = w3s + 512;                                      // [512]
    float* bzs = b1s + 512;                                      // [512]

    const int tid = threadIdx.x;
    const int b0 = blockIdx.x * 2;

    // init constants
    w3s[tid] = W3[tid];
    b1s[tid] = b1[tid];
    bzs[tid] = bih[tid] + bhh[tid];
    hc[tid] = 0.f;

    // Wih (k'=0..63, kk_z=0..7) into SMEM
    {
        const uint4* src = (const uint4*)g_wzp;
        for (int i = tid; i < 8 * 512; i += 512) wihs[i] = src[i];
    }
    // s2 slice into SMEM (padded rows)
    for (int bb = 0; bb < 2; bb++) {
        const uint4* src = (const uint4*)(g_s2 + (size_t)(b0 + bb) * DD * TT);
        for (int i = tid; i < 64 * 64; i += 512) {
            int r = i >> 6, cc = i & 63;
            *((uint4*)(s2s + (size_t)(bb * 64 + r) * S2STRIDE + cc * 8)) = src[i];
        }
    }
    __syncthreads();
    const float b3v = b3[0];

    for (int t = 0; t < TT; t++) {
        // ---- Phase A': s1[b][s] = hc[b].W1col(s) + b1 ; zh[b][j] = h[b].WhhCol(j) ----
        {
            const int s = tid;
            const uint4* w1p = (const uint4*)g_w1p;
            const uint4* whp = (const uint4*)g_wzp + 8 * 512;   // kk_z = 8.. -> Whh
            const ulonglong2* h0 = (const ulonglong2*)hc;        // batch0 [h;c]
            const ulonglong2* h1 = (const ulonglong2*)(hc + 256);
            unsigned long long aW0 = 0, aW1 = 0, aH0 = 0, aH1 = 0;

            // kk 0..15: operands = h (shared by W1 and Whh)
#pragma unroll 4
            for (int kk = 0; kk < 16; kk++) {
                uint4 w = w1p[kk * 512 + s];
                uint4 v = whp[kk * 512 + s];
                ulonglong2 pa = h0[kk * 2], pb = h0[kk * 2 + 1];
                ulonglong2 qa = h1[kk * 2], qb = h1[kk * 2 + 1];
                unsigned long long w01 = bfpair(w.x), w23 = bfpair(w.y);
                unsigned long long w45 = bfpair(w.z), w67 = bfpair(w.w);
                unsigned long long v01 = bfpair(v.x), v23 = bfpair(v.y);
                unsigned long long v45 = bfpair(v.z), v67 = bfpair(v.w);
                ffma2(aW0, w01, pa.x); ffma2(aW0, w23, pa.y);
                ffma2(aW0, w45, pb.x); ffma2(aW0, w67, pb.y);
                ffma2(aW1, w01, qa.x); ffma2(aW1, w23, qa.y);
                ffma2(aW1, w45, qb.x); ffma2(aW1, w67, qb.y);
                ffma2(aH0, v01, pa.x); ffma2(aH0, v23, pa.y);
                ffma2(aH0, v45, pb.x); ffma2(aH0, v67, pb.y);
                ffma2(aH1, v01, qa.x); ffma2(aH1, v23, qa.y);
                ffma2(aH1, v45, qb.x); ffma2(aH1, v67, qb.y);
            }
            // kk 16..31: operands = c (W1 only)
#pragma unroll 4
            for (int kk = 16; kk < 32; kk++) {
                uint4 w = w1p[kk * 512 + s];
                ulonglong2 pa = h0[kk * 2], pb = h0[kk * 2 + 1];
                ulonglong2 qa = h1[kk * 2], qb = h1[kk * 2 + 1];
                unsigned long long w01 = bfpair(w.x), w23 = bfpair(w.y);
                unsigned long long w45 = bfpair(w.z), w67 = bfpair(w.w);
                ffma2(aW0, w01, pa.x); ffma2(aW0, w23, pa.y);
                ffma2(aW0, w45, pb.x); ffma2(aW0, w67, pb.y);
                ffma2(aW1, w01, qa.x); ffma2(aW1, w23, qa.y);
                ffma2(aW1, w45, qb.x); ffma2(aW1, w67, qb.y);
            }
            s1s[s]       = pair_sum(aW0) + b1s[s];
            s1s[512 + s] = pair_sum(aW1) + b1s[s];
            zhs[s]       = pair_sum(aH0) + bzs[s];
            zhs[512 + s] = pair_sum(aH1) + bzs[s];
        }
        __syncthreads();

        // ---- Phase B: e[b][d] = sum_s tanh(s1+s2)*w3 + b3 ----
        {
            const int p = tid >> 2, sub = tid & 3;
            const int bb = p >> 6, d = p & 63;
            const uint4* row = (const uint4*)(s2s + (size_t)(bb * 64 + d) * S2STRIDE);
            const float4* s1f = (const float4*)(s1s + bb * 512);
            const float4* w3f = (const float4*)w3s;
            float acc = 0.f;
#pragma unroll
            for (int it = 0; it < 16; it++) {
                uint4 v = row[it * 4 + sub];
                int f4 = it * 8 + sub * 2;
                float4 sa = s1f[f4], sb = s1f[f4 + 1];
                float4 wa = w3f[f4], wb = w3f[f4 + 1];
                acc = fmaf(tanh_fast(sa.x + bl(v.x)), wa.x, acc);
                acc = fmaf(tanh_fast(sa.y + bh(v.x)), wa.y, acc);
                acc = fmaf(tanh_fast(sa.z + bl(v.y)), wa.z, acc);
                acc = fmaf(tanh_fast(sa.w + bh(v.y)), wa.w, acc);
                acc = fmaf(tanh_fast(sb.x + bl(v.z)), wb.x, acc);
                acc = fmaf(tanh_fast(sb.y + bh(v.z)), wb.y, acc);
                acc = fmaf(tanh_fast(sb.z + bl(v.w)), wb.z, acc);
                acc = fmaf(tanh_fast(sb.w + bh(v.w)), wb.w, acc);
            }
            acc += __shfl_xor_sync(0xffffffffu, acc, 1);
            acc += __shfl_xor_sync(0xffffffffu, acc, 2);
            if (sub == 0) es[bb * 64 + d] = acc + b3v;
        }
        __syncthreads();

        // ---- Phase C: softmax over d, x = a * x_t ----
        if (tid < 64) {
            const int bb = tid >> 5, lane = tid & 31;
            float e0 = es[bb * 64 + lane], e1 = es[bb * 64 + lane + 32];
            float m = fmaxf(e0, e1);
#pragma unroll
            for (int o = 16; o; o >>= 1) m = fmaxf(m, __shfl_xor_sync(0xffffffffu, m, o));
            float p0 = __expf(e0 - m), p1 = __expf(e1 - m);
            float sm = p0 + p1;
#pragma unroll
            for (int o = 16; o; o >>= 1) sm += __shfl_xor_sync(0xffffffffu, sm, o);
            float inv = 1.f / sm;
            const float* dp = din + ((size_t)(b0 + bb) * TT + t) * DD;
            xs[bb * 64 + lane]      = p0 * inv * dp[lane];
            xs[bb * 64 + lane + 32] = p1 * inv * dp[lane + 32];
        }
        __syncthreads();

        // ---- Phase D': z[b][j] = x.WihCol(j) + zh[b][j]  (weights from SMEM) ----
        {
            const int j = tid;
            const ulonglong2* x0 = (const ulonglong2*)xs;
            const ulonglong2* x1 = (const ulonglong2*)(xs + 64);
            unsigned long long a0 = 0, a1 = 0;
#pragma unroll
            for (int kk = 0; kk < 8; kk++) {
                uint4 w = wihs[kk * 512 + j];
                ulonglong2 pa = x0[kk * 2], pb = x0[kk * 2 + 1];
                ulonglong2 qa = x1[kk * 2], qb = x1[kk * 2 + 1];
                unsigned long long w01 = bfpair(w.x), w23 = bfpair(w.y);
                unsigned long long w45 = bfpair(w.z), w67 = bfpair(w.w);
                ffma2(a0, w01, pa.x); ffma2(a0, w23, pa.y);
                ffma2(a0, w45, pb.x); ffma2(a0, w67, pb.y);
                ffma2(a1, w01, qa.x); ffma2(a1, w23, qa.y);
                ffma2(a1, w45, qb.x); ffma2(a1, w67, qb.y);
            }
            zhs[j]       += pair_sum(a0);
            zhs[512 + j] += pair_sum(a1);
        }
        __syncthreads();

        // ---- Phase E: gates, state update, output ----
        if (tid < 256) {
            const int bb = tid >> 7, m = tid & 127;
            float iv = zhs[bb * 512 + m];
            float fv = zhs[bb * 512 + 128 + m];
            float gv = zhs[bb * 512 + 256 + m];
            float ov = zhs[bb * 512 + 384 + m];
            float c = hc[bb * 256 + 128 + m];
            float cn = sigf(fv) * c + sigf(iv) * tanh_ex(gv);
            float hn = sigf(ov) * tanh_ex(cn);
            hc[bb * 256 + 128 + m] = cn;
            hc[bb * 256 + m] = hn;
            out[(((size_t)(b0 + bb)) * TT + t) * HH + m] = hn;
        }
        __syncthreads();
    }
}

// ---------------- launch ----------------
extern "C" void kernel_launch(void* const* d_in, const int* in_sizes, int n_in,
                              void* d_out, int out_size) {
    const float* din = (const float*)d_in[0];
    const float* Wih = (const float*)d_in[1];
    const float* Whh = (const float*)d_in[2];
    const float* bih = (const float*)d_in[3];
    const float* bhh = (const float*)d_in[4];
    const float* W1  = (const float*)d_in[5];
    const float* b1  = (const float*)d_in[6];
    const float* W2  = (const float*)d_in[7];
    const float* b2  = (const float*)d_in[8];
    const float* W3  = (const float*)d_in[9];
    const float* b3  = (const float*)d_in[10];
    float* out = (float*)d_out;

    const int smem_bytes = SM_S2_BYTES + SM_WIH_BYTES +
        (2 * 256 + 2 * 512 + 2 * 512 + 2 * 64 + 2 * 64 + 3 * 512) * 4;
    cudaFuncSetAttribute(scan_kernel, cudaFuncAttributeMaxDynamicSharedMemorySize, smem_bytes);

    pack_weights<<<128, 256>>>(W1, Wih, Whh);
    s2_gemm<<<BB * 4, 256>>>(din, W2, b2);
    scan_kernel<<<BB / 2, 512, smem_bytes>>>(din, b1, bih, bhh, W3, b3, out);
}

// round 4
// speedup vs baseline: 1.1682x; 1.1188x over previous
#include <cuda_runtime.h>
#include <cuda_bf16.h>

#define BB 256
#define TT 512
#define DD 64
#define HH 128
#define NBLK 128

// ---------------- device scratch (static, no allocation) ----------------
__device__ __nv_bfloat16 g_w1p[32 * 512 * 8];   // [kk][s][u], k = kk*8+u in [0,256)
__device__ __nv_bfloat16 g_wzp[24 * 512 * 8];   // [kk][j][u], k' in [0,192): 0..63 Wih, 64..191 Whh
__device__ unsigned g_bar_count = 0;
__device__ unsigned g_bar_flag = 0;

// ---------------- helpers ----------------
__device__ __forceinline__ float tanh_fast(float x) {
    float y;
    asm("tanh.approx.f32 %0, %1;" : "=f"(y) : "f"(x));
    return y;
}
__device__ __forceinline__ float bl(unsigned u) { return __uint_as_float(u << 16); }
__device__ __forceinline__ float bh(unsigned u) { return __uint_as_float(u & 0xffff0000u); }
__device__ __forceinline__ float sigf(float x) { return 1.f / (1.f + __expf(-x)); }
__device__ __forceinline__ float tanh_ex(float x) {
    x = fminf(fmaxf(x, -15.f), 15.f);
    float e = __expf(2.f * x);
    return (e - 1.f) / (e + 1.f);
}
__device__ __forceinline__ unsigned pack_bf2(float a, float b) {
    __nv_bfloat162 t = __floats2bfloat162_rn(a, b);
    return *(unsigned*)&t;
}
__device__ __forceinline__ void ffma2(unsigned long long& acc, unsigned long long ab,
                                      unsigned long long cd) {
    asm("fma.rn.f32x2 %0, %1, %2, %0;" : "+l"(acc) : "l"(ab), "l"(cd));
}
__device__ __forceinline__ unsigned long long bfpair(unsigned u) {
    unsigned long long p;
    asm("{\n\t.reg .b32 lo, hi;\n\t"
        "shl.b32 lo, %1, 16;\n\t"
        "and.b32 hi, %1, 0xff" "ff0000;\n\t"
        "mov.b64 %0, {lo, hi};\n\t}" : "=l"(p) : "r"(u));
    return p;
}
__device__ __forceinline__ unsigned long long mk_pair(float lo, float hi) {
    unsigned long long p;
    asm("mov.b64 %0, {%1, %2};" : "=l"(p) : "f"(lo), "f"(hi));
    return p;
}
__device__ __forceinline__ float pair_lo(unsigned long long p) { return __uint_as_float((unsigned)p); }
__device__ __forceinline__ float pair_hi(unsigned long long p) { return __uint_as_float((unsigned)(p >> 32)); }
__device__ __forceinline__ float pair_sum(unsigned long long p) { return pair_lo(p) + pair_hi(p); }

// ---------------- smem layout ----------------
#define S2STRIDE 544
#define SM_S2_BYTES (2 * 64 * S2STRIDE * 2)      // 139264
#define SM_WIH_BYTES (8 * 512 * 8 * 2)           // 65536
#define SM_FLOATS (512 + 1024 + 1024 + 128 + 128 + 512 + 512 + 512 + 128)  // 4480
#define SM_TOTAL (SM_S2_BYTES + SM_WIH_BYTES + SM_FLOATS * 4)              // 222720

// ---------------- the one kernel ----------------
__global__ void __launch_bounds__(512, 1) fused_kernel(
    const float* __restrict__ din, const float* __restrict__ Wih,
    const float* __restrict__ Whh, const float* __restrict__ bih,
    const float* __restrict__ bhh, const float* __restrict__ W1,
    const float* __restrict__ b1, const float* __restrict__ W2,
    const float* __restrict__ b2, const float* __restrict__ W3,
    const float* __restrict__ b3, float* __restrict__ out) {
    extern __shared__ char smraw[];
    __nv_bfloat16* s2s = (__nv_bfloat16*)smraw;                 // [2*64][544]
    uint4* wihs = (uint4*)(smraw + SM_S2_BYTES);                // [8*512] uint4
    float* hc   = (float*)(smraw + SM_S2_BYTES + SM_WIH_BYTES); // [2][256] : h then c
    float* s1s  = hc + 512;                                      // [2][512]
    float* zhs  = s1s + 1024;                                    // [2][512]
    float* xs   = zhs + 1024;                                    // [2][64]
    float* es   = xs + 128;                                      // [2][64]
    float* w3s  = es + 128;                                      // [512]
    float* b1s  = w3s + 512;                                     // [512]
    float* bzs  = b1s + 512;                                     // [512]
    float* dinb = bzs + 512;                                     // [2][64]

    const int tid = threadIdx.x;
    const int b0 = blockIdx.x * 2;

    // ======== STAGE 1: pack weights (grid-strided across all blocks) ========
    {
        int gidx = blockIdx.x * 512 + tid;
        int gstride = NBLK * 512;
        for (int i = gidx; i < 32 * 512 * 8; i += gstride) {
            int u = i & 7, s = (i >> 3) & 511, kk = i >> 12;
            g_w1p[i] = __float2bfloat16(W1[s * 256 + kk * 8 + u]);
        }
        for (int i = gidx; i < 24 * 512 * 8; i += gstride) {
            int u = i & 7, j = (i >> 3) & 511, kk = i >> 12;
            int k = kk * 8 + u;
            float v = (k < 64) ? Wih[j * 64 + k] : Whh[j * 128 + (k - 64)];
            g_wzp[i] = __float2bfloat16(v);
        }
    }
    // grid barrier (all 128 blocks resident: 1 block/SM, 128 <= 148 SMs)
    __syncthreads();
    if (tid == 0) {
        unsigned f0 = *((volatile unsigned*)&g_bar_flag);
        __threadfence();
        unsigned old = atomicAdd(&g_bar_count, 1);
        if (old == NBLK - 1) {
            g_bar_count = 0;
            __threadfence();
            atomicAdd(&g_bar_flag, 1);
        } else {
            while (*((volatile unsigned*)&g_bar_flag) == f0) { __nanosleep(64); }
        }
        __threadfence();
    }
    __syncthreads();

    // ======== STAGE 2: s2[b,d,s] = sum_t din[b,t,d]*W2[s,t] + b2[s] into SMEM ========
    {
        float* w2st  = (float*)(smraw + SM_S2_BYTES);  // [32][514] staging (73984B < region)
        float* dinst = w2st + 32 * 514;                 // [32][64]
        const int lane = tid & 31, sgrp = tid >> 5;
        const int d0 = lane * 2, sbase = sgrp * 32;

        for (int bb = 0; bb < 2; bb++) {
            const int b = b0 + bb;
            unsigned long long acc[2][16];
#pragma unroll
            for (int p = 0; p < 16; p++) {
                float2 bp = *(const float2*)(b2 + sbase + 2 * p);
                acc[0][p] = mk_pair(bp.x, bp.y);
                acc[1][p] = acc[0][p];
            }
            for (int tc = 0; tc < 16; tc++) {
                const int t0 = tc * 32;
                __syncthreads();
                for (int i = tid; i < 32 * 512; i += 512) {
                    int tt = i & 31, sl = i >> 5;
                    w2st[tt * 514 + sl] = W2[(size_t)sl * TT + t0 + tt];
                }
                for (int i = tid; i < 32 * 64; i += 512) {
                    int tt = i >> 6, dd = i & 63;
                    dinst[tt * 64 + dd] = din[((size_t)b * TT + t0 + tt) * DD + dd];
                }
                __syncthreads();
#pragma unroll 4
                for (int tt = 0; tt < 32; tt++) {
                    float2 av = *(const float2*)&dinst[tt * 64 + d0];
                    unsigned long long ax = mk_pair(av.x, av.x);
                    unsigned long long ay = mk_pair(av.y, av.y);
                    const unsigned long long* wrow =
                        (const unsigned long long*)(w2st + tt * 514 + sbase);
#pragma unroll
                    for (int p = 0; p < 16; p++) {
                        unsigned long long wp = wrow[p];
                        ffma2(acc[0][p], wp, ax);
                        ffma2(acc[1][p], wp, ay);
                    }
                }
            }
            // write results (rows disjoint from staging region)
#pragma unroll
            for (int dl = 0; dl < 2; dl++) {
                unsigned* row = (unsigned*)(s2s + (size_t)(bb * 64 + d0 + dl) * S2STRIDE + sbase);
#pragma unroll
                for (int p = 0; p < 16; p++)
                    row[p] = pack_bf2(pair_lo(acc[dl][p]), pair_hi(acc[dl][p]));
            }
        }
    }
    __syncthreads();

    // ======== STAGE 3: init scan constants (region overlapped staging, init after) ========
    w3s[tid] = W3[tid];
    b1s[tid] = b1[tid];
    bzs[tid] = bih[tid] + bhh[tid];
    hc[tid] = 0.f;
    {
        const uint4* src = (const uint4*)g_wzp;  // Wih = kk 0..7
        for (int i = tid; i < 8 * 512; i += 512) wihs[i] = src[i];
    }
    __syncthreads();
    const float b3v = b3[0];

    // ======== STAGE 4: the scan ========
    for (int t = 0; t < TT; t++) {
        // prefetch din[., t, .] for phase C (latency hidden behind phase A)
        float dval = 0.f;
        if (tid < 128) {
            int bb = tid >> 6, dd = tid & 63;
            dval = din[((size_t)(b0 + bb) * TT + t) * DD + dd];
        }
        // ---- Phase A: s1 = [h;c].W1col + b1 ; zh = h.WhhCol + bz ----
        {
            const int s = tid;
            const uint4* w1p = (const uint4*)g_w1p;
            const uint4* whp = (const uint4*)g_wzp + 8 * 512;
            const ulonglong2* h0 = (const ulonglong2*)hc;
            const ulonglong2* h1 = (const ulonglong2*)(hc + 256);
            unsigned long long aW0 = 0, aW1 = 0, aH0 = 0, aH1 = 0;
#pragma unroll 4
            for (int kk = 0; kk < 16; kk++) {
                uint4 w = w1p[kk * 512 + s];
                uint4 v = whp[kk * 512 + s];
                ulonglong2 pa = h0[kk * 2], pb = h0[kk * 2 + 1];
                ulonglong2 qa = h1[kk * 2], qb = h1[kk * 2 + 1];
                unsigned long long w01 = bfpair(w.x), w23 = bfpair(w.y);
                unsigned long long w45 = bfpair(w.z), w67 = bfpair(w.w);
                unsigned long long v01 = bfpair(v.x), v23 = bfpair(v.y);
                unsigned long long v45 = bfpair(v.z), v67 = bfpair(v.w);
                ffma2(aW0, w01, pa.x); ffma2(aW0, w23, pa.y);
                ffma2(aW0, w45, pb.x); ffma2(aW0, w67, pb.y);
                ffma2(aW1, w01, qa.x); ffma2(aW1, w23, qa.y);
                ffma2(aW1, w45, qb.x); ffma2(aW1, w67, qb.y);
                ffma2(aH0, v01, pa.x); ffma2(aH0, v23, pa.y);
                ffma2(aH0, v45, pb.x); ffma2(aH0, v67, pb.y);
                ffma2(aH1, v01, qa.x); ffma2(aH1, v23, qa.y);
                ffma2(aH1, v45, qb.x); ffma2(aH1, v67, qb.y);
            }
#pragma unroll 4
            for (int kk = 16; kk < 32; kk++) {
                uint4 w = w1p[kk * 512 + s];
                ulonglong2 pa = h0[kk * 2], pb = h0[kk * 2 + 1];
                ulonglong2 qa = h1[kk * 2], qb = h1[kk * 2 + 1];
                unsigned long long w01 = bfpair(w.x), w23 = bfpair(w.y);
                unsigned long long w45 = bfpair(w.z), w67 = bfpair(w.w);
                ffma2(aW0, w01, pa.x); ffma2(aW0, w23, pa.y);
                ffma2(aW0, w45, pb.x); ffma2(aW0, w67, pb.y);
                ffma2(aW1, w01, qa.x); ffma2(aW1, w23, qa.y);
                ffma2(aW1, w45, qb.x); ffma2(aW1, w67, qb.y);
            }
            s1s[s]       = pair_sum(aW0) + b1s[s];
            s1s[512 + s] = pair_sum(aW1) + b1s[s];
            zhs[s]       = pair_sum(aH0) + bzs[s];
            zhs[512 + s] = pair_sum(aH1) + bzs[s];
        }
        if (tid < 128) dinb[tid] = dval;
        __syncthreads();

        // ---- Phase B: e[b][d] = sum_s tanh(s1+s2)*w3 + b3 ----
        {
            const int p = tid >> 2, sub = tid & 3;
            const int bb = p >> 6, d = p & 63;
            const uint4* row = (const uint4*)(s2s + (size_t)(bb * 64 + d) * S2STRIDE);
            const float4* s1f = (const float4*)(s1s + bb * 512);
            const float4* w3f = (const float4*)w3s;
            float acc = 0.f;
#pragma unroll
            for (int it = 0; it < 16; it++) {
                uint4 v = row[it * 4 + sub];
                int f4 = it * 8 + sub * 2;
                float4 sa = s1f[f4], sb = s1f[f4 + 1];
                float4 wa = w3f[f4], wb = w3f[f4 + 1];
                acc = fmaf(tanh_fast(sa.x + bl(v.x)), wa.x, acc);
                acc = fmaf(tanh_fast(sa.y + bh(v.x)), wa.y, acc);
                acc = fmaf(tanh_fast(sa.z + bl(v.y)), wa.z, acc);
                acc = fmaf(tanh_fast(sa.w + bh(v.y)), wa.w, acc);
                acc = fmaf(tanh_fast(sb.x + bl(v.z)), wb.x, acc);
                acc = fmaf(tanh_fast(sb.y + bh(v.z)), wb.y, acc);
                acc = fmaf(tanh_fast(sb.z + bl(v.w)), wb.z, acc);
                acc = fmaf(tanh_fast(sb.w + bh(v.w)), wb.w, acc);
            }
            acc += __shfl_xor_sync(0xffffffffu, acc, 1);
            acc += __shfl_xor_sync(0xffffffffu, acc, 2);
            if (sub == 0) es[bb * 64 + d] = acc + b3v;
        }
        __syncthreads();

        // ---- Phase C: softmax over d, x = a * x_t ----
        if (tid < 64) {
            const int bb = tid >> 5, lane = tid & 31;
            float e0 = es[bb * 64 + lane], e1 = es[bb * 64 + lane + 32];
            float m = fmaxf(e0, e1);
#pragma unroll
            for (int o = 16; o; o >>= 1) m = fmaxf(m, __shfl_xor_sync(0xffffffffu, m, o));
            float p0 = __expf(e0 - m), p1 = __expf(e1 - m);
            float sm = p0 + p1;
#pragma unroll
            for (int o = 16; o; o >>= 1) sm += __shfl_xor_sync(0xffffffffu, sm, o);
            float inv = 1.f / sm;
            xs[bb * 64 + lane]      = p0 * inv * dinb[bb * 64 + lane];
            xs[bb * 64 + lane + 32] = p1 * inv * dinb[bb * 64 + lane + 32];
        }
        __syncthreads();

        // ---- Phase D: z += x.WihCol (weights from SMEM) ----
        {
            const int j = tid;
            const ulonglong2* x0 = (const ulonglong2*)xs;
            const ulonglong2* x1 = (const ulonglong2*)(xs + 64);
            unsigned long long a0 = 0, a1 = 0;
#pragma unroll
            for (int kk = 0; kk < 8; kk++) {
                uint4 w = wihs[kk * 512 + j];
                ulonglong2 pa = x0[kk * 2], pb = x0[kk * 2 + 1];
                ulonglong2 qa = x1[kk * 2], qb = x1[kk * 2 + 1];
                unsigned long long w01 = bfpair(w.x), w23 = bfpair(w.y);
                unsigned long long w45 = bfpair(w.z), w67 = bfpair(w.w);
                ffma2(a0, w01, pa.x); ffma2(a0, w23, pa.y);
                ffma2(a0, w45, pb.x); ffma2(a0, w67, pb.y);
                ffma2(a1, w01, qa.x); ffma2(a1, w23, qa.y);
                ffma2(a1, w45, qb.x); ffma2(a1, w67, qb.y);
            }
            zhs[j]       += pair_sum(a0);
            zhs[512 + j] += pair_sum(a1);
        }
        __syncthreads();

        // ---- Phase E: gates, state update, output ----
        if (tid < 256) {
            const int bb = tid >> 7, m = tid & 127;
            float iv = zhs[bb * 512 + m];
            float fv = zhs[bb * 512 + 128 + m];
            float gv = zhs[bb * 512 + 256 + m];
            float ov = zhs[bb * 512 + 384 + m];
            float c = hc[bb * 256 + 128 + m];
            float cn = sigf(fv) * c + sigf(iv) * tanh_ex(gv);
            float hn = sigf(ov) * tanh_ex(cn);
            hc[bb * 256 + 128 + m] = cn;
            hc[bb * 256 + m] = hn;
            out[(((size_t)(b0 + bb)) * TT + t) * HH + m] = hn;
        }
        __syncthreads();
    }
}

// ---------------- launch ----------------
extern "C" void kernel_launch(void* const* d_in, const int* in_sizes, int n_in,
                              void* d_out, int out_size) {
    const float* din = (const float*)d_in[0];
    const float* Wih = (const float*)d_in[1];
    const float* Whh = (const float*)d_in[2];
    const float* bih = (const float*)d_in[3];
    const float* bhh = (const float*)d_in[4];
    const float* W1  = (const float*)d_in[5];
    const float* b1  = (const float*)d_in[6];
    const float* W2  = (const float*)d_in[7];
    const float* b2  = (const float*)d_in[8];
    const float* W3  = (const float*)d_in[9];
    const float* b3  = (const float*)d_in[10];
    float* out = (float*)d_out;

    cudaFuncSetAttribute(fused_kernel, cudaFuncAttributeMaxDynamicSharedMemorySize, SM_TOTAL);
    fused_kernel<<<NBLK, 512, SM_TOTAL>>>(din, Wih, Whh, bih, bhh, W1, b1, W2, b2, W3, b3, out);
}